// round 10
// baseline (speedup 1.0000x reference)
#include <cuda_runtime.h>
#include <float.h>

// Chamfer distance, B=4, N=M=4096, D=3 — SYMMETRIC tiling: each pair distance
// computed once, feeds BOTH directions.
//   d = ||p||^2 + ||g||^2 - 2 p.g   (full dist in-chain: e = np + w, then 3 FMA2)
// Tile: 512 recon src (4/thread, 128 thr) x 128 gt dst (64 packed pairs, smem).
// Row mins (per src): thread-private, as before.
// Col mins (per dst): lane-rotated dst order -> at each step every lane of a
// warp touches a DISTINCT warp-private smem slot (no races, no shuffles);
// exact fminf -> order-independent -> deterministic.
// Combine across tiles: atomicMax on key = 0x7F7FFFFF - bits(dist>=0); the
// zero-initialized __device__ array is the identity (no init kernel).
// Last CTA decodes, sums fixed-order, resets slots for the next graph replay.

#define BATCH 4
#define NPTS  4096
#define TPB   128
#define NWARP (TPB / 32)                     // 4
#define SRC_PER_THREAD 4
#define SRC_PER_CTA (TPB * SRC_PER_THREAD)   // 512
#define CHUNKS (NPTS / SRC_PER_CTA)          // 8
#define NSPLIT 32
#define SPLIT_PTS (NPTS / NSPLIT)            // 128
#define SPLIT_PAIRS (SPLIT_PTS / 2)          // 64
#define NSLOTS (2 * BATCH * NPTS)            // 32768 (recon then gt)
#define NCTAS (CHUNKS * NSPLIT * BATCH)      // 1024

__device__ unsigned int g_maxkey[NSLOTS];    // 0 == key(FLT_MAX): identity
__device__ unsigned int g_count = 0;

typedef unsigned long long u64;

__device__ __forceinline__ u64 pk(float a, float b) {
    u64 r;
    asm("mov.b64 %0, {%1, %2};" : "=l"(r) : "f"(a), "f"(b));
    return r;
}
__device__ __forceinline__ void upk(u64 v, float& lo, float& hi) {
    asm("mov.b64 {%0, %1}, %2;" : "=f"(lo), "=f"(hi) : "l"(v));
}
__device__ __forceinline__ u64 fma2(u64 a, u64 b, u64 c) {
    u64 d;
    asm("fma.rn.f32x2 %0, %1, %2, %3;" : "=l"(d) : "l"(a), "l"(b), "l"(c));
    return d;
}
__device__ __forceinline__ u64 add2(u64 a, u64 b) {
    u64 d;
    asm("add.rn.f32x2 %0, %1, %2;" : "=l"(d) : "l"(a), "l"(b));
    return d;
}
__device__ __forceinline__ unsigned int dist_key(float m) {
    return 0x7F7FFFFFu - __float_as_uint(fmaxf(m, 0.0f));
}

__global__ void __launch_bounds__(TPB, 7) chamfer_sym_kernel(
    const float* __restrict__ recon,
    const float* __restrict__ gt,
    float* __restrict__ out)
{
    // Packed gt pairs: per pair p, sdst[2p]={x0|x1,y0|y1}, sdst[2p+1]={z0|z1,w0|w1}
    __shared__ ulonglong2 sdst[2 * SPLIT_PAIRS];       // 2 KB
    __shared__ float2 s_col[NWARP * SPLIT_PAIRS];      // 2 KB: per-warp col mins

    const int chunk = blockIdx.x;   // recon chunk (0..7)
    const int split = blockIdx.y;   // gt split  (0..31)
    const int b     = blockIdx.z;   // batch
    const int tid   = threadIdx.x;
    const int lane  = tid & 31;
    const int w     = tid >> 5;

    const float* gtb = gt + ((size_t)b * NPTS + (size_t)split * SPLIT_PTS) * 3;

    // Prologue: 128 threads pack 64 gt pairs (2 smem entries per pair).
    {
        const int p = tid >> 1;
        const int h = tid & 1;
        const float* g0 = gtb + 6 * p;
        float x0 = g0[0], y0 = g0[1], z0 = g0[2];
        float x1 = g0[3], y1 = g0[4], z1 = g0[5];
        if (h == 0) {
            sdst[2 * p] = make_ulonglong2(pk(x0, x1), pk(y0, y1));
        } else {
            float w0 = fmaf(x0, x0, fmaf(y0, y0, z0 * z0));
            float w1 = fmaf(x1, x1, fmaf(y1, y1, z1 * z1));
            sdst[2 * p + 1] = make_ulonglong2(pk(z0, z1), pk(w0, w1));
        }
    }
    // Warp-private column-min init (no cross-warp hazard).
    s_col[w * SPLIT_PAIRS + lane]      = make_float2(FLT_MAX, FLT_MAX);
    s_col[w * SPLIT_PAIRS + lane + 32] = make_float2(FLT_MAX, FLT_MAX);
    __syncthreads();

    // Four recon src points per thread (stride TPB).
    u64 qx[4], qy[4], qz[4], np2[4];
    const float* rb = recon + ((size_t)b * NPTS + (size_t)chunk * SRC_PER_CTA) * 3;
    #pragma unroll
    for (int k = 0; k < 4; ++k) {
        const float* sp = rb + (k * TPB + tid) * 3;
        float px = sp[0], py = sp[1], pz = sp[2];
        qx[k] = pk(-2.0f * px, -2.0f * px);
        qy[k] = pk(-2.0f * py, -2.0f * py);
        qz[k] = pk(-2.0f * pz, -2.0f * pz);
        float np = fmaf(px, px, fmaf(py, py, pz * pz));
        np2[k] = pk(np, np);
    }

    float ml0 = FLT_MAX, mh0 = FLT_MAX;
    float ml1 = FLT_MAX, mh1 = FLT_MAX;
    float ml2 = FLT_MAX, mh2 = FLT_MAX;
    float ml3 = FLT_MAX, mh3 = FLT_MAX;

    // Lane-rotated scan: lane l processes pair (jj+l)&63 at step jj, so all
    // 32 lanes touch distinct col slots every step.
    int pj = lane;
    #pragma unroll 4
    for (int jj = 0; jj < SPLIT_PAIRS; ++jj) {
        ulonglong2 A = sdst[2 * pj];       // {xx, yy}
        ulonglong2 B = sdst[2 * pj + 1];   // {zz, ww}

        u64 d0 = fma2(qx[0], A.x, fma2(qy[0], A.y, fma2(qz[0], B.x, add2(np2[0], B.y))));
        u64 d1 = fma2(qx[1], A.x, fma2(qy[1], A.y, fma2(qz[1], B.x, add2(np2[1], B.y))));
        u64 d2 = fma2(qx[2], A.x, fma2(qy[2], A.y, fma2(qz[2], B.x, add2(np2[2], B.y))));
        u64 d3 = fma2(qx[3], A.x, fma2(qy[3], A.y, fma2(qz[3], B.x, add2(np2[3], B.y))));

        float l0, h0, l1, h1, l2, h2, l3, h3;
        upk(d0, l0, h0); upk(d1, l1, h1); upk(d2, l2, h2); upk(d3, l3, h3);

        // Row mins (full distances).
        ml0 = fminf(ml0, l0); mh0 = fminf(mh0, h0);
        ml1 = fminf(ml1, l1); mh1 = fminf(mh1, h1);
        ml2 = fminf(ml2, l2); mh2 = fminf(mh2, h2);
        ml3 = fminf(ml3, l3); mh3 = fminf(mh3, h3);

        // Column mins: min over this thread's 4 srcs, merge into warp slot.
        float cl = fminf(fminf(l0, l1), fminf(l2, l3));
        float ch = fminf(fminf(h0, h1), fminf(h2, h3));
        float2 cm = s_col[w * SPLIT_PAIRS + pj];
        cm.x = fminf(cm.x, cl);
        cm.y = fminf(cm.y, ch);
        s_col[w * SPLIT_PAIRS + pj] = cm;

        pj = (pj + 1) & (SPLIT_PAIRS - 1);
    }

    // Row results -> recon slots.
    const int rbase = b * NPTS + chunk * SRC_PER_CTA + tid;
    atomicMax(&g_maxkey[rbase + 0 * TPB], dist_key(fminf(ml0, mh0)));
    atomicMax(&g_maxkey[rbase + 1 * TPB], dist_key(fminf(ml1, mh1)));
    atomicMax(&g_maxkey[rbase + 2 * TPB], dist_key(fminf(ml2, mh2)));
    atomicMax(&g_maxkey[rbase + 3 * TPB], dist_key(fminf(ml3, mh3)));

    // Column results: merge 4 warp arrays, -> gt slots.
    __syncthreads();
    {
        const float* sc = (const float*)s_col;   // [warp][128] floats
        float v = sc[tid];
        v = fminf(v, sc[128 + tid]);
        v = fminf(v, sc[256 + tid]);
        v = fminf(v, sc[384 + tid]);
        atomicMax(&g_maxkey[BATCH * NPTS + b * NPTS + split * SPLIT_PTS + tid],
                  dist_key(v));
    }

    // Elect last CTA to finalize.
    __shared__ unsigned int s_last;
    __threadfence();
    __syncthreads();
    if (tid == 0) {
        unsigned int old = atomicAdd(&g_count, 1u);
        s_last = (old == NCTAS - 1) ? 1u : 0u;
    }
    __syncthreads();

    if (s_last) {
        __threadfence();   // all atomics visible
        float acc = 0.0f;
        const uint4* mv = (const uint4*)g_maxkey;
        #pragma unroll 4
        for (int s = tid; s < NSLOTS / 4; s += TPB) {
            uint4 v = mv[s];
            acc += __uint_as_float(0x7F7FFFFFu - v.x)
                 + __uint_as_float(0x7F7FFFFFu - v.y)
                 + __uint_as_float(0x7F7FFFFFu - v.z)
                 + __uint_as_float(0x7F7FFFFFu - v.w);
        }
        __shared__ float sred[TPB];
        sred[tid] = acc;
        __syncthreads();

        // Reset slots to the identity (0) for the next graph replay.
        uint4* mw = (uint4*)g_maxkey;
        const uint4 z4 = make_uint4(0u, 0u, 0u, 0u);
        #pragma unroll 4
        for (int s = tid; s < NSLOTS / 4; s += TPB) mw[s] = z4;

        #pragma unroll
        for (int s = TPB / 2; s > 0; s >>= 1) {
            if (tid < s) sred[tid] += sred[tid + s];
            __syncthreads();
        }
        if (tid == 0) {
            out[0] = sred[0] / (float)NSLOTS;   // == (mean1 + mean2) / 2
            g_count = 0;                        // reset for next replay
        }
    }
}

extern "C" void kernel_launch(void* const* d_in, const int* in_sizes, int n_in,
                              void* d_out, int out_size)
{
    const float* recon = (const float*)d_in[0];
    const float* gt    = (const float*)d_in[1];
    float* out = (float*)d_out;

    dim3 grid(CHUNKS, NSPLIT, BATCH);   // 8 x 32 x 4 = 1024 CTAs
    chamfer_sym_kernel<<<grid, TPB>>>(recon, gt, out);
}